// round 1
// baseline (speedup 1.0000x reference)
#include <cuda_runtime.h>
#include <math.h>

#define NN 10000
#define NE 160000
#define H 128
#define NRBF 32
#define NG 128
#define NOUT 65
#define TE 16
#define NTILE (NE/TE)

// ---------------- scratch (device globals; no allocation) ----------------
__device__ float g_x[NN*H];
__device__ float g_vec[NN*3*H];
__device__ float g_dx[NN*H];
__device__ float g_dvec[NN*3*H];
__device__ float g_vmix[NN*3*H];   // reused as v2 in the final stage
__device__ float g_dirn[NE*3];
__device__ float g_rbf[NE*NRBF];
__device__ float g_pooled[NG*NOUT];

__device__ __forceinline__ float silu_f(float v){ return v / (1.0f + expf(-v)); }

__device__ __forceinline__ void red4(float* p, float a, float b, float c, float d){
  asm volatile("red.global.add.v4.f32 [%0], {%1,%2,%3,%4};"
               :: "l"(p), "f"(a), "f"(b), "f"(c), "f"(d) : "memory");
}

// ---------------- init: x = embed[z], vec = 0, pooled = 0 ----------------
__global__ void k_init(const int* __restrict__ z, const float* __restrict__ emb){
  int idx = blockIdx.x*blockDim.x + threadIdx.x;
  if (idx < NN*3*H) g_vec[idx] = 0.0f;
  if (idx < NN*H){ int n = idx >> 7, h = idx & 127; g_x[idx] = emb[z[n]*H + h]; }
  if (idx < NG*NOUT) g_pooled[idx] = 0.0f;
}

// ---------------- per-layer zero of accumulators ----------------
__global__ void k_zero(){
  int idx = blockIdx.x*blockDim.x + threadIdx.x;
  if (idx < NN*3*H) g_dvec[idx] = 0.0f;
  if (idx < NN*H)   g_dx[idx]   = 0.0f;
}

// ---------------- vec += dvec ----------------
__global__ void k_vecadd(){
  int idx = blockIdx.x*blockDim.x + threadIdx.x;
  if (idx < NN*3*H) g_vec[idx] += g_dvec[idx];
}

// ---------------- edge geometry: dirn + rbf (once) ----------------
__global__ void k_edgegeom(const int* __restrict__ ei, const float* __restrict__ pos){
  int e = blockIdx.x*blockDim.x + threadIdx.x;
  if (e >= NE) return;
  int s = ei[e], d = ei[NE + e];
  float dx = pos[d*3+0]-pos[s*3+0];
  float dy = pos[d*3+1]-pos[s*3+1];
  float dz = pos[d*3+2]-pos[s*3+2];
  float r = sqrtf(dx*dx + dy*dy + dz*dz + 1e-8f);
  float inv = 1.0f/r;
  g_dirn[e*3+0] = dx*inv; g_dirn[e*3+1] = dy*inv; g_dirn[e*3+2] = dz*inv;
  float m0 = expf(-5.0f);
  float dm = (1.0f - m0) / (float)(NRBF - 1);
  float tb = (2.0f/(float)NRBF) * (1.0f - m0);
  float beta = 1.0f/(tb*tb);
  float cut = (r < 5.0f) ? 0.5f*(cosf(3.14159265358979323846f * r * 0.2f) + 1.0f) : 0.0f;
  float al = expf(-r);
  #pragma unroll
  for (int i = 0; i < NRBF; ++i){
    float df = al - (m0 + (float)i * dm);
    g_rbf[e*NRBF + i] = cut * expf(-beta*df*df);
  }
}

// ---------------- generic 128x128 row GEMM: Y[rows] (+)= X[rows] @ W ----------------
template<bool ACC>
__global__ void gemm128(const float* __restrict__ X, const float* __restrict__ W,
                        float* __restrict__ Y, int rows){
  extern __shared__ float sm[];
  float* Ws = sm;            // 128*128
  float* Xs = Ws + H*H;      // 16*128
  int tid = threadIdx.x, warp = tid >> 5, lane = tid & 31;
  for (int i = tid; i < H*H; i += 128) Ws[i] = W[i];
  int ntiles = rows / 16;
  for (int t = blockIdx.x; t < ntiles; t += gridDim.x){
    __syncthreads();
    int r0 = t * 16;
    for (int i = tid; i < 16*H; i += 128) Xs[i] = X[r0*H + i];
    __syncthreads();
    float acc[4][4];
    #pragma unroll
    for (int r = 0; r < 4; ++r){ acc[r][0]=acc[r][1]=acc[r][2]=acc[r][3]=0.0f; }
    #pragma unroll 4
    for (int k = 0; k < H; ++k){
      float4 w = *(const float4*)&Ws[k*H + lane*4];
      #pragma unroll
      for (int r = 0; r < 4; ++r){
        float xv = Xs[(warp*4 + r)*H + k];
        acc[r][0] += xv*w.x; acc[r][1] += xv*w.y; acc[r][2] += xv*w.z; acc[r][3] += xv*w.w;
      }
    }
    #pragma unroll
    for (int r = 0; r < 4; ++r){
      int row = r0 + warp*4 + r;
      float4* yp = (float4*)&Y[row*H + lane*4];
      float4 v = make_float4(acc[r][0], acc[r][1], acc[r][2], acc[r][3]);
      if (ACC){ float4 o = *yp; v.x += o.x; v.y += o.y; v.z += o.z; v.w += o.w; }
      *yp = v;
    }
  }
}

// ---------------- fused edge kernel (per layer) ----------------
// filt = rbf@W_rbf ; t = x[src]*filt ; phi = silu(t@W1)
// red: dx[dst] += phi ; dvec[dst][c] += vmix[src][c]*filt + phi*dirn[c]
__global__ void k_edge(const int* __restrict__ ei, const float* __restrict__ Wrbf,
                       const float* __restrict__ W1){
  extern __shared__ float sm[];
  float* Wr   = sm;                   // 32*128
  float* W1s  = Wr  + NRBF*H;         // 128*128
  float* rbfs = W1s + H*H;            // 16*32
  float* ts   = rbfs + TE*NRBF;       // 16*128
  float* dirs = ts   + TE*H;          // 16*3
  int*   srcs = (int*)(dirs + TE*3);  // 16
  int*   dsts = srcs + TE;            // 16
  int tid = threadIdx.x, warp = tid >> 5, lane = tid & 31;
  for (int i = tid; i < NRBF*H; i += 128) Wr[i]  = Wrbf[i];
  for (int i = tid; i < H*H;   i += 128) W1s[i] = W1[i];

  for (int t = blockIdx.x; t < NTILE; t += gridDim.x){
    __syncthreads();
    int e0 = t * TE;
    if (tid < TE){ srcs[tid] = ei[e0 + tid]; dsts[tid] = ei[NE + e0 + tid]; }
    if (tid < TE*3) dirs[tid] = g_dirn[e0*3 + tid];
    for (int i = tid; i < TE*NRBF; i += 128) rbfs[i] = g_rbf[e0*NRBF + i];
    __syncthreads();

    // filt (kept in registers) : warp handles edges warp*4..+3, lane handles cols lane*4..+3
    float f[4][4];
    #pragma unroll
    for (int e = 0; e < 4; ++e){ f[e][0]=f[e][1]=f[e][2]=f[e][3]=0.0f; }
    #pragma unroll
    for (int r = 0; r < NRBF; ++r){
      float4 w = *(const float4*)&Wr[r*H + lane*4];
      #pragma unroll
      for (int e = 0; e < 4; ++e){
        float rv = rbfs[(warp*4 + e)*NRBF + r];
        f[e][0] += rv*w.x; f[e][1] += rv*w.y; f[e][2] += rv*w.z; f[e][3] += rv*w.w;
      }
    }
    // t = x[src] * filt -> smem
    #pragma unroll
    for (int e = 0; e < 4; ++e){
      int s = srcs[warp*4 + e];
      float4 xv = *(const float4*)&g_x[s*H + lane*4];
      float4 tv = make_float4(xv.x*f[e][0], xv.y*f[e][1], xv.z*f[e][2], xv.w*f[e][3]);
      *(float4*)&ts[(warp*4 + e)*H + lane*4] = tv;
    }
    __syncthreads();

    // phi = silu(t @ W1)
    float p[4][4];
    #pragma unroll
    for (int e = 0; e < 4; ++e){ p[e][0]=p[e][1]=p[e][2]=p[e][3]=0.0f; }
    #pragma unroll 4
    for (int k = 0; k < H; ++k){
      float4 w = *(const float4*)&W1s[k*H + lane*4];
      #pragma unroll
      for (int e = 0; e < 4; ++e){
        float tv = ts[(warp*4 + e)*H + k];
        p[e][0] += tv*w.x; p[e][1] += tv*w.y; p[e][2] += tv*w.z; p[e][3] += tv*w.w;
      }
    }
    #pragma unroll
    for (int e = 0; e < 4; ++e){
      p[e][0] = silu_f(p[e][0]); p[e][1] = silu_f(p[e][1]);
      p[e][2] = silu_f(p[e][2]); p[e][3] = silu_f(p[e][3]);
    }

    // scatter via vector reductions
    #pragma unroll
    for (int e = 0; e < 4; ++e){
      int el = warp*4 + e;
      int d = dsts[el], s = srcs[el];
      red4(&g_dx[d*H + lane*4], p[e][0], p[e][1], p[e][2], p[e][3]);
      float dc0 = dirs[el*3+0], dc1 = dirs[el*3+1], dc2 = dirs[el*3+2];
      float dcs[3] = {dc0, dc1, dc2};
      #pragma unroll
      for (int c = 0; c < 3; ++c){
        float4 vm = *(const float4*)&g_vmix[(s*3 + c)*H + lane*4];
        red4(&g_dvec[(d*3 + c)*H + lane*4],
             vm.x*f[e][0] + p[e][0]*dcs[c],
             vm.y*f[e][1] + p[e][1]*dcs[c],
             vm.z*f[e][2] + p[e][2]*dcs[c],
             vm.w*f[e][3] + p[e][3]*dcs[c]);
      }
    }
  }
}

// ---------------- final: vnorm, silu MLP, out head, pooled atomics ----------------
__global__ void k_final(const int* __restrict__ batch, const float* __restrict__ Wa,
                        const float* __restrict__ ba, const float* __restrict__ Wb,
                        const float* __restrict__ bb){
  extern __shared__ float sm[];
  float* Was = sm;               // 256*128
  float* Wbs = Was + 256*H;      // 128*65
  float* bas = Wbs + H*NOUT;     // 128
  float* bbs = bas + H;          // 65
  float* xs  = bbs + NOUT;       // 128
  float* vns = xs + H;           // 128
  float* as_ = vns + H;          // 128
  int tid = threadIdx.x;
  for (int i = tid; i < 256*H; i += 128) Was[i] = Wa[i];
  for (int i = tid; i < H*NOUT; i += 128) Wbs[i] = Wb[i];
  if (tid < H)    bas[tid] = ba[tid];
  if (tid < NOUT) bbs[tid] = bb[tid];

  for (int n = blockIdx.x; n < NN; n += gridDim.x){
    __syncthreads();
    {
      float a0 = g_vmix[(n*3+0)*H + tid];   // g_vmix reused as v2
      float a1 = g_vmix[(n*3+1)*H + tid];
      float a2 = g_vmix[(n*3+2)*H + tid];
      vns[tid] = sqrtf(a0*a0 + a1*a1 + a2*a2 + 1e-8f);
      xs[tid]  = g_x[n*H + tid];
    }
    __syncthreads();
    float acc = bas[tid];
    #pragma unroll 4
    for (int k = 0; k < H; ++k) acc += xs[k]  * Was[k*H + tid];
    #pragma unroll 4
    for (int k = 0; k < H; ++k) acc += vns[k] * Was[(H + k)*H + tid];
    as_[tid] = silu_f(acc);
    __syncthreads();
    if (tid < NOUT){
      float o = bbs[tid];
      #pragma unroll 4
      for (int h = 0; h < H; ++h) o += as_[h] * Wbs[h*NOUT + tid];
      atomicAdd(&g_pooled[batch[n]*NOUT + tid], o);
    }
  }
}

// ---------------- write output: mu (128x64) then clipped log_var (128) ----------------
__global__ void k_out(float* __restrict__ out){
  int idx = blockIdx.x*blockDim.x + threadIdx.x;
  if (idx < NG*64){
    int g = idx >> 6, j = idx & 63;
    out[idx] = g_pooled[g*NOUT + j];
  } else if (idx < NG*64 + NG){
    int g = idx - NG*64;
    float v = g_pooled[g*NOUT + 64];
    out[idx] = fminf(fmaxf(v, -10.0f), 2.0f);
  }
}

// ---------------- launch ----------------
extern "C" void kernel_launch(void* const* d_in, const int* in_sizes, int n_in,
                              void* d_out, int out_size){
  const int*   z     = (const int*)  d_in[0];
  const float* pos   = (const float*)d_in[1];
  const int*   batch = (const int*)  d_in[2];
  const int*   ei    = (const int*)  d_in[3];
  const float* emb   = (const float*)d_in[4];
  const float* Wrbf  = (const float*)d_in[5];
  const float* W1    = (const float*)d_in[6];
  const float* Wo    = (const float*)d_in[7];
  const float* Wv    = (const float*)d_in[8];
  const float* Wvec2 = (const float*)d_in[10];
  const float* Wa    = (const float*)d_in[11];
  const float* ba    = (const float*)d_in[12];
  const float* Wb    = (const float*)d_in[13];
  const float* bb    = (const float*)d_in[14];
  float* out = (float*)d_out;

  float *p_x, *p_vec, *p_dx, *p_dvec, *p_vmix;
  cudaGetSymbolAddress((void**)&p_x,    g_x);
  cudaGetSymbolAddress((void**)&p_vec,  g_vec);
  cudaGetSymbolAddress((void**)&p_dx,   g_dx);
  cudaGetSymbolAddress((void**)&p_dvec, g_dvec);
  cudaGetSymbolAddress((void**)&p_vmix, g_vmix);

  const size_t edge_smem  = (size_t)(NRBF*H + H*H + TE*NRBF + TE*H + TE*3 + 2*TE) * sizeof(float);
  const size_t gemm_smem  = (size_t)(H*H + 16*H) * sizeof(float);
  const size_t final_smem = (size_t)(256*H + H*NOUT + H + NOUT + 3*H) * sizeof(float);
  cudaFuncSetAttribute(k_edge,         cudaFuncAttributeMaxDynamicSharedMemorySize, (int)edge_smem);
  cudaFuncSetAttribute(gemm128<false>, cudaFuncAttributeMaxDynamicSharedMemorySize, (int)gemm_smem);
  cudaFuncSetAttribute(gemm128<true>,  cudaFuncAttributeMaxDynamicSharedMemorySize, (int)gemm_smem);
  cudaFuncSetAttribute(k_final,        cudaFuncAttributeMaxDynamicSharedMemorySize, (int)final_smem);

  const int ZB = (NN*3*H + 255) / 256;

  k_init<<<ZB, 256>>>(z, emb);
  k_edgegeom<<<(NE + 255)/256, 256>>>(ei, pos);

  for (int l = 0; l < 2; ++l){
    k_zero<<<ZB, 256>>>();
    gemm128<false><<<444, 128, gemm_smem>>>(p_vec, Wv + l*H*H, p_vmix, NN*3);
    k_edge<<<296, 128, edge_smem>>>(ei, Wrbf + l*NRBF*H, W1 + l*H*H);
    gemm128<true><<<444, 128, gemm_smem>>>(p_dx, Wo + l*H*H, p_x, NN);
    k_vecadd<<<ZB, 256>>>();
  }

  // v2 = vec @ Wvec2 (reuse g_vmix)
  gemm128<false><<<444, 128, gemm_smem>>>(p_vec, Wvec2, p_vmix, NN*3);
  k_final<<<148, 128, final_smem>>>(batch, Wa, ba, Wb, bb);
  k_out<<<(NG*64 + NG + 255)/256, 256>>>(out);
}

// round 4
// speedup vs baseline: 1.8850x; 1.8850x over previous
#include <cuda_runtime.h>
#include <math.h>

#define NN 10000
#define NE 160000
#define H 128
#define NRBF 32
#define NG 128
#define NOUT 65
#define PADX 132

// ---------------- scratch (device globals; no allocation) ----------------
__device__ float g_x[NN*H];
__device__ float g_vec[NN*3*H];
__device__ float g_dx[NN*H];        // also reused as vnorm buffer at the end
__device__ float g_dvec[NN*3*H];    // also reused as 'a' activations at the end
__device__ float g_vmix[NN*3*H];    // reused as v2 in the final stage
__device__ float g_dirn[NE*3];
__device__ float g_rbf[NE*NRBF];
__device__ float g_pooled[NG*NOUT];

__device__ __forceinline__ float silu_f(float v){ return v / (1.0f + expf(-v)); }

__device__ __forceinline__ void red4(float* p, float a, float b, float c, float d){
  asm volatile("red.global.add.v4.f32 [%0], {%1,%2,%3,%4};"
               :: "l"(p), "f"(a), "f"(b), "f"(c), "f"(d) : "memory");
}

// ---------------- init: x = embed[z], vec/vmix/pooled = 0 ----------------
__global__ void k_init(const int* __restrict__ z, const float* __restrict__ emb){
  int idx = blockIdx.x*blockDim.x + threadIdx.x;
  if (idx < NN*3*H){ g_vec[idx] = 0.0f; g_vmix[idx] = 0.0f; }
  if (idx < NN*H){ int n = idx >> 7, h = idx & 127; g_x[idx] = emb[z[n]*H + h]; }
  if (idx < NG*NOUT) g_pooled[idx] = 0.0f;
}

__global__ void k_zero(){
  int idx = blockIdx.x*blockDim.x + threadIdx.x;
  if (idx < NN*3*H) g_dvec[idx] = 0.0f;
  if (idx < NN*H)   g_dx[idx]   = 0.0f;
}

__global__ void k_vecadd(){
  int idx = blockIdx.x*blockDim.x + threadIdx.x;
  if (idx < NN*3*H) g_vec[idx] += g_dvec[idx];
}

// ---------------- edge geometry: dirn + rbf (once) ----------------
__global__ void k_edgegeom(const int* __restrict__ ei, const float* __restrict__ pos){
  int e = blockIdx.x*blockDim.x + threadIdx.x;
  if (e >= NE) return;
  int s = ei[e], d = ei[NE + e];
  float dx = pos[d*3+0]-pos[s*3+0];
  float dy = pos[d*3+1]-pos[s*3+1];
  float dz = pos[d*3+2]-pos[s*3+2];
  float r = sqrtf(dx*dx + dy*dy + dz*dz + 1e-8f);
  float inv = 1.0f/r;
  g_dirn[e*3+0] = dx*inv; g_dirn[e*3+1] = dy*inv; g_dirn[e*3+2] = dz*inv;
  float m0 = expf(-5.0f);
  float dm = (1.0f - m0) / (float)(NRBF - 1);
  float tb = (2.0f/(float)NRBF) * (1.0f - m0);
  float beta = 1.0f/(tb*tb);
  float cut = (r < 5.0f) ? 0.5f*(cosf(3.14159265358979323846f * r * 0.2f) + 1.0f) : 0.0f;
  float al = expf(-r);
  #pragma unroll
  for (int i = 0; i < NRBF; ++i){
    float df = al - (m0 + (float)i * dm);
    g_rbf[e*NRBF + i] = cut * expf(-beta*df*df);
  }
}

// ---------------- node GEMM: Y[rows,128] (+)= X[rows,128] @ W[128,128] ----------------
// 64-row x 128-col tile per block, 128 threads, 8x8 per thread.
template<bool ACC>
__global__ __launch_bounds__(128, 2)
void gemm_nk(const float* __restrict__ X, const float* __restrict__ W,
             float* __restrict__ Y, int rows){
  extern __shared__ float sm[];
  float* Ws = sm;            // 128*128
  float* Xs = Ws + H*H;      // 64*PADX
  int tid = threadIdx.x;
  int tcol = tid & 15, trow = tid >> 4;   // 16 col-groups x 8 row-groups
  for (int i = tid; i < H*H; i += 128) Ws[i] = W[i];
  int ntiles = (rows + 63) >> 6;
  for (int t = blockIdx.x; t < ntiles; t += gridDim.x){
    __syncthreads();
    int r0 = t << 6;
    for (int i = tid; i < 64*H; i += 128){
      int rr = i >> 7, kk = i & 127;
      Xs[rr*PADX + kk] = (r0 + rr < rows) ? X[(size_t)(r0+rr)*H + kk] : 0.0f;
    }
    __syncthreads();
    float acc[8][8];
    #pragma unroll
    for (int r=0;r<8;++r){
      #pragma unroll
      for (int c=0;c<8;++c) acc[r][c]=0.f;
    }
    #pragma unroll 2
    for (int k0 = 0; k0 < H; k0 += 4){
      float4 xv[8];
      #pragma unroll
      for (int r=0;r<8;++r) xv[r] = *(const float4*)&Xs[(trow*8+r)*PADX + k0];
      #pragma unroll
      for (int kk=0;kk<4;++kk){
        float4 wa = *(const float4*)&Ws[(k0+kk)*H + tcol*8];
        float4 wb = *(const float4*)&Ws[(k0+kk)*H + tcol*8+4];
        #pragma unroll
        for (int r=0;r<8;++r){
          float x = (kk==0)?xv[r].x:(kk==1)?xv[r].y:(kk==2)?xv[r].z:xv[r].w;
          acc[r][0]+=x*wa.x; acc[r][1]+=x*wa.y; acc[r][2]+=x*wa.z; acc[r][3]+=x*wa.w;
          acc[r][4]+=x*wb.x; acc[r][5]+=x*wb.y; acc[r][6]+=x*wb.z; acc[r][7]+=x*wb.w;
        }
      }
    }
    #pragma unroll
    for (int r=0;r<8;++r){
      int row = r0 + trow*8 + r;
      if (row < rows){
        float4* yp = (float4*)&Y[(size_t)row*H + tcol*8];
        float4 v0 = make_float4(acc[r][0],acc[r][1],acc[r][2],acc[r][3]);
        float4 v1 = make_float4(acc[r][4],acc[r][5],acc[r][6],acc[r][7]);
        if (ACC){
          float4 o0=yp[0], o1=yp[1];
          v0.x+=o0.x; v0.y+=o0.y; v0.z+=o0.z; v0.w+=o0.w;
          v1.x+=o1.x; v1.y+=o1.y; v1.z+=o1.z; v1.w+=o1.w;
        }
        yp[0]=v0; yp[1]=v1;
      }
    }
  }
}

// ---------------- fused edge kernel (per layer) ----------------
// 512 threads, 128 edges/tile, thread owns 4 edges x 8 cols.
// filt = rbf@W_rbf ; t = x[src]*filt ; phi = silu(t@W1)
// red: dx[dst] += phi ; dvec[dst][c] += vmix[src][c]*filt + phi*dirn[c]
#define ETILE 128
#define NTILES (NE/ETILE)
__global__ __launch_bounds__(512, 1)
void k_edge(const int* __restrict__ ei, const float* __restrict__ Wrbf,
            const float* __restrict__ W1){
  extern __shared__ float sm[];
  float* W1s  = sm;                   // 128*128
  float* Wr   = W1s + H*H;            // 32*128
  float* ts   = Wr + NRBF*H;          // 128*PADX
  float* rbfs = ts + ETILE*PADX;      // 128*36
  float* dirs = rbfs + ETILE*36;      // 384
  int*   srcs = (int*)(dirs + 384);   // 128
  int*   dsts = srcs + ETILE;         // 128
  int tid = threadIdx.x;
  int tcol = tid & 15, trow = tid >> 4;   // 16 col-groups x 32 row-groups (4 edges each)
  for (int i = tid; i < H*H;    i += 512) W1s[i] = W1[i];
  for (int i = tid; i < NRBF*H; i += 512) Wr[i]  = Wrbf[i];

  for (int t = blockIdx.x; t < NTILES; t += gridDim.x){
    __syncthreads();
    int e0 = t * ETILE;
    if (tid < ETILE) srcs[tid] = ei[e0 + tid];
    else if (tid < 2*ETILE) dsts[tid - ETILE] = ei[NE + e0 + (tid - ETILE)];
    for (int i = tid; i < ETILE*3; i += 512) dirs[i] = g_dirn[(size_t)e0*3 + i];
    for (int i = tid; i < ETILE*NRBF; i += 512){
      int e = i >> 5, r = i & 31;
      rbfs[e*36 + r] = g_rbf[(size_t)e0*NRBF + i];
    }
    __syncthreads();

    // ---- filt = rbf @ W_rbf (register-resident, 4 edges x 8 cols) ----
    float f[4][8];
    #pragma unroll
    for (int e=0;e<4;++e){
      #pragma unroll
      for (int c=0;c<8;++c) f[e][c]=0.f;
    }
    #pragma unroll
    for (int k0 = 0; k0 < NRBF; k0 += 4){
      float4 xv[4];
      #pragma unroll
      for (int e=0;e<4;++e) xv[e] = *(const float4*)&rbfs[(trow*4+e)*36 + k0];
      #pragma unroll
      for (int kk=0;kk<4;++kk){
        float4 wa = *(const float4*)&Wr[(k0+kk)*H + tcol*8];
        float4 wb = *(const float4*)&Wr[(k0+kk)*H + tcol*8+4];
        #pragma unroll
        for (int e=0;e<4;++e){
          float x = (kk==0)?xv[e].x:(kk==1)?xv[e].y:(kk==2)?xv[e].z:xv[e].w;
          f[e][0]+=x*wa.x; f[e][1]+=x*wa.y; f[e][2]+=x*wa.z; f[e][3]+=x*wa.w;
          f[e][4]+=x*wb.x; f[e][5]+=x*wb.y; f[e][6]+=x*wb.z; f[e][7]+=x*wb.w;
        }
      }
    }

    // ---- ts = x[src] * filt ----
    #pragma unroll
    for (int e=0;e<4;++e){
      int s = srcs[trow*4+e];
      const float* xp = &g_x[(size_t)s*H + tcol*8];
      float4 xa = *(const float4*)xp;
      float4 xb = *(const float4*)(xp+4);
      float* tp = &ts[(trow*4+e)*PADX + tcol*8];
      *(float4*)tp     = make_float4(xa.x*f[e][0], xa.y*f[e][1], xa.z*f[e][2], xa.w*f[e][3]);
      *(float4*)(tp+4) = make_float4(xb.x*f[e][4], xb.y*f[e][5], xb.z*f[e][6], xb.w*f[e][7]);
    }
    __syncthreads();

    // ---- phi = silu(ts @ W1) ----
    float p[4][8];
    #pragma unroll
    for (int e=0;e<4;++e){
      #pragma unroll
      for (int c=0;c<8;++c) p[e][c]=0.f;
    }
    #pragma unroll 2
    for (int k0 = 0; k0 < H; k0 += 4){
      float4 xv[4];
      #pragma unroll
      for (int e=0;e<4;++e) xv[e] = *(const float4*)&ts[(trow*4+e)*PADX + k0];
      #pragma unroll
      for (int kk=0;kk<4;++kk){
        float4 wa = *(const float4*)&W1s[(k0+kk)*H + tcol*8];
        float4 wb = *(const float4*)&W1s[(k0+kk)*H + tcol*8+4];
        #pragma unroll
        for (int e=0;e<4;++e){
          float x = (kk==0)?xv[e].x:(kk==1)?xv[e].y:(kk==2)?xv[e].z:xv[e].w;
          p[e][0]+=x*wa.x; p[e][1]+=x*wa.y; p[e][2]+=x*wa.z; p[e][3]+=x*wa.w;
          p[e][4]+=x*wb.x; p[e][5]+=x*wb.y; p[e][6]+=x*wb.z; p[e][7]+=x*wb.w;
        }
      }
    }
    #pragma unroll
    for (int e=0;e<4;++e){
      #pragma unroll
      for (int c=0;c<8;++c) p[e][c] = silu_f(p[e][c]);
    }

    // ---- scatter (vector reductions) ----
    #pragma unroll
    for (int e=0;e<4;++e){
      int el = trow*4 + e;
      int d = dsts[el], s = srcs[el];
      red4(&g_dx[(size_t)d*H + tcol*8],   p[e][0], p[e][1], p[e][2], p[e][3]);
      red4(&g_dx[(size_t)d*H + tcol*8+4], p[e][4], p[e][5], p[e][6], p[e][7]);
      float dc[3] = {dirs[el*3+0], dirs[el*3+1], dirs[el*3+2]};
      #pragma unroll
      for (int c=0;c<3;++c){
        const float* vmp = &g_vmix[((size_t)s*3 + c)*H + tcol*8];
        float4 va = *(const float4*)vmp;
        float4 vb = *(const float4*)(vmp+4);
        float* dvp = &g_dvec[((size_t)d*3 + c)*H + tcol*8];
        red4(dvp,   va.x*f[e][0] + p[e][0]*dc[c], va.y*f[e][1] + p[e][1]*dc[c],
                    va.z*f[e][2] + p[e][2]*dc[c], va.w*f[e][3] + p[e][3]*dc[c]);
        red4(dvp+4, vb.x*f[e][4] + p[e][4]*dc[c], vb.y*f[e][5] + p[e][5]*dc[c],
                    vb.z*f[e][6] + p[e][6]*dc[c], vb.w*f[e][7] + p[e][7]*dc[c]);
      }
    }
  }
}

// ---------------- vnorm: g_dx[n,h] = sqrt(sum_c v2[n,c,h]^2 + eps) ----------------
__global__ void k_vnorm(){
  int idx = blockIdx.x*blockDim.x + threadIdx.x;
  if (idx >= NN*H) return;
  int n = idx >> 7, h = idx & 127;
  float a0 = g_vmix[((size_t)n*3+0)*H + h];
  float a1 = g_vmix[((size_t)n*3+1)*H + h];
  float a2 = g_vmix[((size_t)n*3+2)*H + h];
  g_dx[idx] = sqrtf(a0*a0 + a1*a1 + a2*a2 + 1e-8f);
}

// ---------------- a = silu([x, vnorm] @ Wa + ba) -> g_dvec ----------------
// 256 threads, 64-row tile, thread owns 4 rows x 8 cols; K = 256
#define PADA 264
__global__ __launch_bounds__(256, 1)
void k_mlp_a(const float* __restrict__ Wa, const float* __restrict__ ba){
  extern __shared__ float sm[];
  float* Was = sm;               // 256*128
  float* Xs  = Was + 256*H;      // 64*PADA
  float* bas = Xs + 64*PADA;     // 128
  int tid = threadIdx.x;
  int tcol = tid & 15, trow = tid >> 4;   // 16 col-groups x 16 row-groups (4 rows each)
  for (int i = tid; i < 256*H; i += 256) Was[i] = Wa[i];
  if (tid < H) bas[tid] = ba[tid];
  int ntiles = (NN + 63) >> 6;
  for (int t = blockIdx.x; t < ntiles; t += gridDim.x){
    __syncthreads();
    int r0 = t << 6;
    for (int i = tid; i < 64*256; i += 256){
      int rr = i >> 8, kk = i & 255;
      float v = 0.0f;
      if (r0 + rr < NN)
        v = (kk < H) ? g_x[(size_t)(r0+rr)*H + kk] : g_dx[(size_t)(r0+rr)*H + (kk-H)];
      Xs[rr*PADA + kk] = v;
    }
    __syncthreads();
    float acc[4][8];
    #pragma unroll
    for (int r=0;r<4;++r){
      #pragma unroll
      for (int c=0;c<8;++c) acc[r][c]=0.f;
    }
    #pragma unroll 2
    for (int k0 = 0; k0 < 256; k0 += 4){
      float4 xv[4];
      #pragma unroll
      for (int r=0;r<4;++r) xv[r] = *(const float4*)&Xs[(trow*4+r)*PADA + k0];
      #pragma unroll
      for (int kk=0;kk<4;++kk){
        float4 wa = *(const float4*)&Was[(k0+kk)*H + tcol*8];
        float4 wb = *(const float4*)&Was[(k0+kk)*H + tcol*8+4];
        #pragma unroll
        for (int r=0;r<4;++r){
          float x = (kk==0)?xv[r].x:(kk==1)?xv[r].y:(kk==2)?xv[r].z:xv[r].w;
          acc[r][0]+=x*wa.x; acc[r][1]+=x*wa.y; acc[r][2]+=x*wa.z; acc[r][3]+=x*wa.w;
          acc[r][4]+=x*wb.x; acc[r][5]+=x*wb.y; acc[r][6]+=x*wb.z; acc[r][7]+=x*wb.w;
        }
      }
    }
    #pragma unroll
    for (int r=0;r<4;++r){
      int row = r0 + trow*4 + r;
      if (row < NN){
        float* ap = &g_dvec[(size_t)row*H + tcol*8];
        #pragma unroll
        for (int c=0;c<8;++c) ap[c] = silu_f(acc[r][c] + bas[tcol*8+c]);
      }
    }
  }
}

// ---------------- out = a @ Wb + bb, pooled atomics by batch ----------------
__global__ void k_poolout(const int* __restrict__ batch, const float* __restrict__ Wb,
                          const float* __restrict__ bb){
  extern __shared__ float sm[];
  float* Wbs = sm;               // 128*65
  float* bbs = Wbs + H*NOUT;     // 65
  float* as_ = bbs + NOUT;       // 128
  int tid = threadIdx.x;
  for (int i = tid; i < H*NOUT; i += 128) Wbs[i] = Wb[i];
  if (tid < NOUT) bbs[tid] = bb[tid];
  for (int n = blockIdx.x; n < NN; n += gridDim.x){
    __syncthreads();
    as_[tid] = g_dvec[(size_t)n*H + tid];
    __syncthreads();
    if (tid < NOUT){
      float o = bbs[tid];
      #pragma unroll 4
      for (int h = 0; h < H; ++h) o += as_[h] * Wbs[h*NOUT + tid];
      atomicAdd(&g_pooled[batch[n]*NOUT + tid], o);
    }
  }
}

// ---------------- write output: mu (128x64) then clipped log_var (128) ----------------
__global__ void k_out(float* __restrict__ out){
  int idx = blockIdx.x*blockDim.x + threadIdx.x;
  if (idx < NG*64){
    int g = idx >> 6, j = idx & 63;
    out[idx] = g_pooled[g*NOUT + j];
  } else if (idx < NG*64 + NG){
    int g = idx - NG*64;
    float v = g_pooled[g*NOUT + 64];
    out[idx] = fminf(fmaxf(v, -10.0f), 2.0f);
  }
}

// ---------------- launch ----------------
extern "C" void kernel_launch(void* const* d_in, const int* in_sizes, int n_in,
                              void* d_out, int out_size){
  const int*   z     = (const int*)  d_in[0];
  const float* pos   = (const float*)d_in[1];
  const int*   batch = (const int*)  d_in[2];
  const int*   ei    = (const int*)  d_in[3];
  const float* emb   = (const float*)d_in[4];
  const float* Wrbf  = (const float*)d_in[5];
  const float* W1    = (const float*)d_in[6];
  const float* Wo    = (const float*)d_in[7];
  const float* Wv    = (const float*)d_in[8];
  const float* Wvec2 = (const float*)d_in[10];
  const float* Wa    = (const float*)d_in[11];
  const float* ba    = (const float*)d_in[12];
  const float* Wb    = (const float*)d_in[13];
  const float* bb    = (const float*)d_in[14];
  float* out = (float*)d_out;

  float *p_x, *p_vec, *p_dx, *p_dvec, *p_vmix;
  cudaGetSymbolAddress((void**)&p_x,    g_x);
  cudaGetSymbolAddress((void**)&p_vec,  g_vec);
  cudaGetSymbolAddress((void**)&p_dx,   g_dx);
  cudaGetSymbolAddress((void**)&p_dvec, g_dvec);
  cudaGetSymbolAddress((void**)&p_vmix, g_vmix);

  const size_t gemm_smem = (size_t)(H*H + 64*PADX) * sizeof(float);
  const size_t edge_smem = (size_t)(H*H + NRBF*H + ETILE*PADX + ETILE*36 + 384) * sizeof(float)
                         + 2*ETILE*sizeof(int);
  const size_t mlpa_smem = (size_t)(256*H + 64*PADA + H) * sizeof(float);
  const size_t pool_smem = (size_t)(H*NOUT + NOUT + H) * sizeof(float);

  cudaFuncSetAttribute(gemm_nk<false>, cudaFuncAttributeMaxDynamicSharedMemorySize, (int)gemm_smem);
  cudaFuncSetAttribute(gemm_nk<true>,  cudaFuncAttributeMaxDynamicSharedMemorySize, (int)gemm_smem);
  cudaFuncSetAttribute(k_edge,         cudaFuncAttributeMaxDynamicSharedMemorySize, (int)edge_smem);
  cudaFuncSetAttribute(k_mlp_a,        cudaFuncAttributeMaxDynamicSharedMemorySize, (int)mlpa_smem);
  cudaFuncSetAttribute(k_poolout,      cudaFuncAttributeMaxDynamicSharedMemorySize, (int)pool_smem);

  const int ZB = (NN*3*H + 255) / 256;

  k_init<<<ZB, 256>>>(z, emb);
  k_edgegeom<<<(NE + 255)/256, 256>>>(ei, pos);

  for (int l = 0; l < 2; ++l){
    k_zero<<<ZB, 256>>>();
    if (l > 0)  // layer 0: vec == 0, g_vmix pre-zeroed by k_init
      gemm_nk<false><<<296, 128, gemm_smem>>>(p_vec, Wv + (size_t)l*H*H, p_vmix, NN*3);
    k_edge<<<148, 512, edge_smem>>>(ei, Wrbf + (size_t)l*NRBF*H, W1 + (size_t)l*H*H);
    gemm_nk<true><<<296, 128, gemm_smem>>>(p_dx, Wo + (size_t)l*H*H, p_x, NN);
    k_vecadd<<<ZB, 256>>>();
  }

  // v2 = vec @ Wvec2 (into g_vmix)
  gemm_nk<false><<<296, 128, gemm_smem>>>(p_vec, Wvec2, p_vmix, NN*3);
  k_vnorm<<<(NN*H + 255)/256, 256>>>();
  k_mlp_a<<<157, 256, mlpa_smem>>>(Wa, ba);
  k_poolout<<<592, 128, pool_smem>>>(batch, Wb, bb);
  k_out<<<(NG*64 + NG + 255)/256, 256>>>(out);
}